// round 13
// baseline (speedup 1.0000x reference)
#include <cuda_runtime.h>
#include <cuda_bf16.h>
#include <cuda_fp16.h>
#include <mma.h>
#include <cstdint>

using namespace nvcuda;

// Problem constants
#define BB 4
#define TT 1024
#define EE 1024
#define HH 16
#define HD 64
#define MULT 2
#define SS (TT*MULT)
static constexpr float QSCALE = 0.125f;  // HD^-0.5

// Scratch (allocation-free rule: __device__ globals)
__device__ __half g_xf[BB*TT*EE];              // fp16 x
__device__ __half g_Wqf[EE*EE];
__device__ __half g_Wkf[MULT*EE*EE];
__device__ __half g_Wvf[MULT*EE*EE];
__device__ __half g_Wof[EE*EE];
__device__ __half g_Qf[BB*TT*EE];              // fp16 scaled q
__device__ __half g_Kf[BB*SS*EE];
__device__ __half g_Vf[BB*SS*EE];
__device__ __half g_AOf[BB*TT*EE];             // fp16 attention output

// ---------------------------------------------------------------------------
// Elementwise fp32 -> fp16 convert. n4 = n/4.
// ---------------------------------------------------------------------------
__global__ __launch_bounds__(256) void cvt_f16(
    const float* __restrict__ src, __half* __restrict__ dst, int n4)
{
    int i = blockIdx.x * blockDim.x + threadIdx.x;
    if (i >= n4) return;
    float4 v = ((const float4*)src)[i];
    ((__half2*)dst)[i*2]   = __floats2half2_rn(v.x, v.y);
    ((__half2*)dst)[i*2+1] = __floats2half2_rn(v.z, v.w);
}

// ---------------------------------------------------------------------------
// fp16 single-term GEMM (fp32 accum):  C = (A W^T + bias) * scale.
// OMODE 0: fp32 out (C). 2: fp16 out (Cf).  (R12 proven)
// 256 threads = 8 warps in 4x2 grid; warp tile 32x64; 2 CTAs/SM.
// ---------------------------------------------------------------------------
#define LDH 40
#define MATH_ (128*LDH)
#define SH_SMEM (2*2*MATH_*2)

template<int OMODE>
__global__ __launch_bounds__(256, 2) void sgemm_f16(
    const __half* __restrict__ A, const __half* __restrict__ W,
    const float* __restrict__ bias, float* __restrict__ C,
    __half* __restrict__ Cf,
    int N, int K, float scale)
{
    extern __shared__ __half smh[];

    const int tid = threadIdx.x;
    const int m0 = blockIdx.y * 128;
    const int n0 = blockIdx.x * 128;
    const int wid = tid >> 5;
    const int wm = wid >> 1;
    const int wn = wid & 1;

    wmma::fragment<wmma::accumulator, 16, 16, 16, float> acc[2][4];
#pragma unroll
    for (int i = 0; i < 2; i++)
#pragma unroll
        for (int j = 0; j < 4; j++) wmma::fill_fragment(acc[i][j], 0.f);

    const __half* gsrc[2];
    gsrc[0] = A + (size_t)m0 * K;
    gsrc[1] = W + (size_t)n0 * K;
    const int lr  = tid >> 2;
    const int lc8 = (tid & 3) * 8;

#define H_LOAD(dst4, kc) { \
    _Pragma("unroll") \
    for (int mtx = 0; mtx < 2; mtx++) \
        _Pragma("unroll") \
        for (int t = 0; t < 2; t++) \
            dst4[mtx][t] = *(const uint4*)(gsrc[mtx] + (size_t)(lr + t*64)*K + (kc) + lc8); }

#define H_STORE(bufbase, src4) { \
    _Pragma("unroll") \
    for (int mtx = 0; mtx < 2; mtx++) \
        _Pragma("unroll") \
        for (int t = 0; t < 2; t++) \
            *(uint4*)(bufbase + mtx*MATH_ + (lr + t*64)*LDH + lc8) = src4[mtx][t]; }

    {
        uint4 v[2][2];
        H_LOAD(v, 0);
        H_STORE(smh, v);
    }
    __syncthreads();

    const int NC = K >> 5;
    for (int c = 0; c < NC; c++) {
        const bool more = (c + 1 < NC);
        uint4 v[2][2];
        if (more) H_LOAD(v, (c + 1) * 32);

        {
            const __half* buf = smh + (size_t)(c & 1) * 2 * MATH_;
            const __half* sA = buf;
            const __half* sW = buf + MATH_;
#pragma unroll
            for (int kf = 0; kf < 2; kf++) {
                const int k0 = kf * 16;
                wmma::fragment<wmma::matrix_a, 16,16,16, __half, wmma::row_major> af[2];
#pragma unroll
                for (int i = 0; i < 2; i++)
                    wmma::load_matrix_sync(af[i], sA + (wm*32 + i*16)*LDH + k0, LDH);
#pragma unroll
                for (int j = 0; j < 4; j++) {
                    wmma::fragment<wmma::matrix_b, 16,16,16, __half, wmma::col_major> bf;
                    wmma::load_matrix_sync(bf, sW + (wn*64 + j*16)*LDH + k0, LDH);
#pragma unroll
                    for (int i = 0; i < 2; i++)
                        wmma::mma_sync(acc[i][j], af[i], bf, acc[i][j]);
                }
            }
        }
        if (more) {
            __half* buf = smh + (size_t)((c + 1) & 1) * 2 * MATH_;
            H_STORE(buf, v);
        }
        __syncthreads();
    }

    float* ep = (float*)smh + wid * (16*20);
    const int lane = tid & 31;
#pragma unroll
    for (int i = 0; i < 2; i++) {
#pragma unroll
        for (int j = 0; j < 4; j++) {
            wmma::store_matrix_sync(ep, acc[i][j], 20, wmma::mem_row_major);
            __syncwarp();
#pragma unroll
            for (int e = 0; e < 8; e++) {
                int idx = lane * 8 + e;
                int r = idx >> 4, cc = idx & 15;
                int m = m0 + wm*32 + i*16 + r;
                int n = n0 + wn*64 + j*16 + cc;
                float v = (ep[r*20 + cc] + bias[n]) * scale;
                if (OMODE == 0) {
                    C[(size_t)m * N + n] = v;
                } else {
                    Cf[(size_t)m * N + n] = __float2half_rn(v);
                }
            }
            __syncwarp();
        }
    }
}

// ---------------------------------------------------------------------------
// Flash attention v3: 128 queries x 128 keys per tile, fp16 single-term.
// 512 threads = 16 warps.
// QK: warp (wm 0..3, wn 0..3) -> 32x32 S block (2x2 frags), 1:1 load:MMA.
// PV: warp (wm2 0..3, wn2 0..3) -> 32x16 O block (2 frags).
// grid (T/128, H, B) = (8,16,4). Smem 125.4 KB, 1 CTA/SM.
// ---------------------------------------------------------------------------
#define LDQ 72
#define LDK 72
#define LDSF 136
#define OFF_Q  0                  // half 128x72 = 18432
#define OFF_K  18432              // half 128x72 = 18432
#define OFF_V  36864              // half 128x72 = 18432
#define OFF_S  55296              // float 128x136 = 69632 (aliased by P, O)
#define OFF_L  124928             // 128 floats
#define FL_SMEM 125440

__global__ __launch_bounds__(512) void flash_f16(
    const __half* __restrict__ Qf, const __half* __restrict__ Kf,
    const __half* __restrict__ Vf, const float* __restrict__ mask,
    __half* __restrict__ AOf)
{
    extern __shared__ char smraw[];
    __half* sQ = (__half*)(smraw + OFF_Q);
    __half* sK = (__half*)(smraw + OFF_K);
    __half* sV = (__half*)(smraw + OFF_V);
    float*  sS = (float*)(smraw + OFF_S);
    __half* sP = (__half*)(smraw + OFF_S);    // alias (half 128x136 = 34816)
    float*  sO = (float*)(smraw + OFF_S);     // alias (float 128x72 = 36864)
    float*  sL = (float*)(smraw + OFF_L);

    const int tid = threadIdx.x;
    const int t0 = blockIdx.x * 128;
    const int h  = blockIdx.y;
    const int b  = blockIdx.z;
    const int wid = tid >> 5;
    const int wm = wid >> 2, wn = wid & 3;      // QK: 32x32 block
    const int srow = tid >> 2;                  // softmax row 0..127
    const int sc   = (tid & 3) * 32;            // softmax col base

    // Q tile: 128x64 halves = 1024 uint4 slots, 2 per thread
    {
        const __half* q = Qf + ((size_t)(b*TT + t0)) * EE + h*HD;
#pragma unroll
        for (int t = 0; t < 2; t++) {
            int slot = tid + t*512;
            int r = slot >> 3, c8 = (slot & 7) * 8;
            *(uint4*)&sQ[r*LDQ + c8] = *(const uint4*)(q + (size_t)r*EE + c8);
        }
        if (tid < 128) sL[tid] = 0.f;
    }

    wmma::fragment<wmma::accumulator, 16, 16, 16, float> oacc[2];
    wmma::fill_fragment(oacc[0], 0.f);
    wmma::fill_fragment(oacc[1], 0.f);

    const __half* kb = Kf + (size_t)b * SS * EE + h*HD;
    const __half* vb = Vf + (size_t)b * SS * EE + h*HD;
    const float* mrow = mask + ((size_t)(b*TT + t0 + srow)) * TT + sc;

    for (int st = 0; st < SS/128; st++) {
        const int sb = st * 128;
        const int s0b = sb & (TT - 1);

        __syncthreads();
        // K/V tiles: 128x64 halves each = 1024 uint4 slots, 2 per thread each
#pragma unroll
        for (int t = 0; t < 2; t++) {
            int slot = tid + t*512;
            int r = slot >> 3, c8 = (slot & 7) * 8;
            size_t go = (size_t)(sb + r) * EE + c8;
            *(uint4*)&sK[r*LDK + c8] = *(const uint4*)(kb + go);
            *(uint4*)&sV[r*LDK + c8] = *(const uint4*)(vb + go);
        }
        __syncthreads();

        // S = Q K^T: warp block 32x32, 2x2 frags
        {
            wmma::fragment<wmma::accumulator, 16, 16, 16, float> sacc[2][2];
#pragma unroll
            for (int i = 0; i < 2; i++)
#pragma unroll
                for (int j = 0; j < 2; j++) wmma::fill_fragment(sacc[i][j], 0.f);
#pragma unroll
            for (int k = 0; k < 4; k++) {
                wmma::fragment<wmma::matrix_a, 16,16,16, __half, wmma::row_major> af[2];
                wmma::fragment<wmma::matrix_b, 16,16,16, __half, wmma::col_major> bf[2];
#pragma unroll
                for (int i = 0; i < 2; i++)
                    wmma::load_matrix_sync(af[i], sQ + (wm*32 + i*16)*LDQ + k*16, LDQ);
#pragma unroll
                for (int j = 0; j < 2; j++)
                    wmma::load_matrix_sync(bf[j], sK + (wn*32 + j*16)*LDK + k*16, LDK);
#pragma unroll
                for (int i = 0; i < 2; i++)
#pragma unroll
                    for (int j = 0; j < 2; j++)
                        wmma::mma_sync(sacc[i][j], af[i], bf[j], sacc[i][j]);
            }
#pragma unroll
            for (int i = 0; i < 2; i++)
#pragma unroll
                for (int j = 0; j < 2; j++)
                    wmma::store_matrix_sync(sS + (wm*32 + i*16)*LDSF + wn*32 + j*16,
                                            sacc[i][j], LDSF, wmma::mem_row_major);
        }
        __syncthreads();

        // softmax: p = exp(S + mask); 4 threads per row, 32 cols each
        {
            float p[32];
            const float* mr = mrow + s0b;
            float ls = 0.f;
#pragma unroll
            for (int jv = 0; jv < 8; jv++) {
                float4 mv = *(const float4*)(mr + jv*4);
                float e0 = __expf(sS[srow*LDSF + sc + jv*4 + 0] + mv.x);
                float e1 = __expf(sS[srow*LDSF + sc + jv*4 + 1] + mv.y);
                float e2 = __expf(sS[srow*LDSF + sc + jv*4 + 2] + mv.z);
                float e3 = __expf(sS[srow*LDSF + sc + jv*4 + 3] + mv.w);
                p[jv*4+0] = e0; p[jv*4+1] = e1; p[jv*4+2] = e2; p[jv*4+3] = e3;
                ls += e0 + e1 + e2 + e3;
            }
            ls += __shfl_xor_sync(0xffffffffu, ls, 1);
            ls += __shfl_xor_sync(0xffffffffu, ls, 2);
            __syncthreads();   // all S reads done before P overwrite
#pragma unroll
            for (int k2 = 0; k2 < 16; k2++) {
                __half2 pr = __floats2half2_rn(p[2*k2], p[2*k2+1]);
                *(__half2*)&sP[srow*LDSF + sc + 2*k2] = pr;
            }
            if ((tid & 3) == 0) sL[srow] += ls;
        }
        __syncthreads();

        // O += P V: warp block 32 rows x 16 cols (wm2=wm rows band, wn2=wn cols)
#pragma unroll
        for (int k = 0; k < 8; k++) {
            wmma::fragment<wmma::matrix_b, 16,16,16, __half, wmma::row_major> vf;
            wmma::load_matrix_sync(vf, sV + (k*16)*LDK + wn*16, LDK);
#pragma unroll
            for (int i = 0; i < 2; i++) {
                wmma::fragment<wmma::matrix_a, 16,16,16, __half, wmma::row_major> pf;
                wmma::load_matrix_sync(pf, sP + (wm*32 + i*16)*LDSF + k*16, LDSF);
                wmma::mma_sync(oacc[i], pf, vf, oacc[i]);
            }
        }
    }

    __syncthreads();
    wmma::store_matrix_sync(sO + (wm*32 + 0)*LDQ + wn*16, oacc[0], LDQ, wmma::mem_row_major);
    wmma::store_matrix_sync(sO + (wm*32 + 16)*LDQ + wn*16, oacc[1], LDQ, wmma::mem_row_major);
    __syncthreads();

    // write out fp16: AO[b, t0+r, h*HD + c] = sO / l  (128 rows x 64 cols)
    {
        const int r = tid >> 2;
        const int cb = (tid & 3) * 16;
        const float inv = 1.f / sL[r];
        __half* ob = AOf + ((size_t)(b*TT + t0 + r)) * EE + h*HD + cb;
#pragma unroll
        for (int v = 0; v < 4; v++) {
            float4 o = *(const float4*)&sO[r*LDQ + cb + v*4];
            __half2 p0 = __floats2half2_rn(o.x*inv, o.y*inv);
            __half2 p1 = __floats2half2_rn(o.z*inv, o.w*inv);
            *(__half2*)(ob + v*4)     = p0;
            *(__half2*)(ob + v*4 + 2) = p1;
        }
    }
}

// ---------------------------------------------------------------------------
extern "C" void kernel_launch(void* const* d_in, const int* in_sizes, int n_in,
                              void* d_out, int out_size) {
    const float* x    = (const float*)d_in[0];
    const float* mask = (const float*)d_in[1];
    const float* Wq   = (const float*)d_in[2];
    const float* bq   = (const float*)d_in[3];
    const float* Wk   = (const float*)d_in[4];
    const float* bk   = (const float*)d_in[5];
    const float* Wv   = (const float*)d_in[6];
    const float* bv   = (const float*)d_in[7];
    const float* Wo   = (const float*)d_in[8];
    const float* bo   = (const float*)d_in[9];
    float* out = (float*)d_out;

    __half *xf, *Wqf, *Wkf, *Wvf, *Wof, *Qfp, *Kfp, *Vfp, *AOfp;
    cudaGetSymbolAddress((void**)&xf, g_xf);
    cudaGetSymbolAddress((void**)&Wqf, g_Wqf);
    cudaGetSymbolAddress((void**)&Wkf, g_Wkf);
    cudaGetSymbolAddress((void**)&Wvf, g_Wvf);
    cudaGetSymbolAddress((void**)&Wof, g_Wof);
    cudaGetSymbolAddress((void**)&Qfp, g_Qf);
    cudaGetSymbolAddress((void**)&Kfp, g_Kf);
    cudaGetSymbolAddress((void**)&Vfp, g_Vf);
    cudaGetSymbolAddress((void**)&AOfp, g_AOf);

    static bool attr_done = false;
    if (!attr_done) {
        cudaFuncSetAttribute(sgemm_f16<0>, cudaFuncAttributeMaxDynamicSharedMemorySize, SH_SMEM);
        cudaFuncSetAttribute(sgemm_f16<2>, cudaFuncAttributeMaxDynamicSharedMemorySize, SH_SMEM);
        cudaFuncSetAttribute(flash_f16, cudaFuncAttributeMaxDynamicSharedMemorySize, FL_SMEM);
        attr_done = true;
    }

    // 1) convert inputs to fp16
    {
        int nx = BB*TT*EE/4;
        cvt_f16<<<(nx+255)/256, 256>>>(x, xf, nx);
        int nw1 = EE*EE/4;
        cvt_f16<<<(nw1+255)/256, 256>>>(Wq, Wqf, nw1);
        cvt_f16<<<(nw1+255)/256, 256>>>(Wo, Wof, nw1);
        int nw2 = MULT*EE*EE/4;
        cvt_f16<<<(nw2+255)/256, 256>>>(Wk, Wkf, nw2);
        cvt_f16<<<(nw2+255)/256, 256>>>(Wv, Wvf, nw2);
    }

    dim3 gblk(256);
    // 2) QKV projections (fp16 single-term GEMMs)
    sgemm_f16<2><<<dim3(EE/128, (BB*TT)/128), gblk, SH_SMEM>>>(
        xf, Wqf, bq, nullptr, Qfp, EE, EE, QSCALE);
    sgemm_f16<2><<<dim3((MULT*EE)/128, (BB*TT)/128), gblk, SH_SMEM>>>(
        xf, Wkf, bk, nullptr, Kfp, MULT*EE, EE, 1.f);
    sgemm_f16<2><<<dim3((MULT*EE)/128, (BB*TT)/128), gblk, SH_SMEM>>>(
        xf, Wvf, bv, nullptr, Vfp, MULT*EE, EE, 1.f);
    // 3) flash attention (fp16 single, 128-q tiles) -> fp16 AO
    flash_f16<<<dim3(TT/128, HH, BB), dim3(512), FL_SMEM>>>(
        Qfp, Kfp, Vfp, mask, AOfp);
    // 4) output projection (fp16 single-term, fp32 out)
    sgemm_f16<0><<<dim3(EE/128, (BB*TT)/128), gblk, SH_SMEM>>>(
        AOfp, Wof, bo, out, nullptr, EE, EE, 1.f);
}

// round 14
// speedup vs baseline: 1.2719x; 1.2719x over previous
#include <cuda_runtime.h>
#include <cuda_bf16.h>
#include <cuda_fp16.h>
#include <mma.h>
#include <cstdint>

using namespace nvcuda;

// Problem constants
#define BB 4
#define TT 1024
#define EE 1024
#define HH 16
#define HD 64
#define MULT 2
#define SS (TT*MULT)
static constexpr float QSCALE = 0.125f;  // HD^-0.5

// Scratch (allocation-free rule: __device__ globals)
__device__ __half g_xf[BB*TT*EE];              // fp16 x
__device__ __half g_Wqf[EE*EE];
__device__ __half g_Wkf[MULT*EE*EE];
__device__ __half g_Wvf[MULT*EE*EE];
__device__ __half g_Wof[EE*EE];
__device__ __half g_Qf[BB*TT*EE];              // fp16 scaled q
__device__ __half g_Kf[BB*SS*EE];
__device__ __half g_Vf[BB*SS*EE];
__device__ __half g_AOf[BB*TT*EE];             // fp16 attention output

// ---------------------------------------------------------------------------
// Elementwise fp32 -> fp16 convert. n4 = n/4.
// ---------------------------------------------------------------------------
__global__ __launch_bounds__(256) void cvt_f16(
    const float* __restrict__ src, __half* __restrict__ dst, int n4)
{
    int i = blockIdx.x * blockDim.x + threadIdx.x;
    if (i >= n4) return;
    float4 v = ((const float4*)src)[i];
    ((__half2*)dst)[i*2]   = __floats2half2_rn(v.x, v.y);
    ((__half2*)dst)[i*2+1] = __floats2half2_rn(v.z, v.w);
}

// ---------------------------------------------------------------------------
// fp16 single-term GEMM (fp32 accum):  C = (A W^T + bias) * scale.
// OMODE 0: fp32 out (C). 2: fp16 out (Cf).  (R12 proven)
// 256 threads = 8 warps in 4x2 grid; warp tile 32x64; 2 CTAs/SM.
// ---------------------------------------------------------------------------
#define LDH 40
#define MATH_ (128*LDH)
#define SH_SMEM (2*2*MATH_*2)

template<int OMODE>
__global__ __launch_bounds__(256, 2) void sgemm_f16(
    const __half* __restrict__ A, const __half* __restrict__ W,
    const float* __restrict__ bias, float* __restrict__ C,
    __half* __restrict__ Cf,
    int N, int K, float scale)
{
    extern __shared__ __half smh[];

    const int tid = threadIdx.x;
    const int m0 = blockIdx.y * 128;
    const int n0 = blockIdx.x * 128;
    const int wid = tid >> 5;
    const int wm = wid >> 1;
    const int wn = wid & 1;

    wmma::fragment<wmma::accumulator, 16, 16, 16, float> acc[2][4];
#pragma unroll
    for (int i = 0; i < 2; i++)
#pragma unroll
        for (int j = 0; j < 4; j++) wmma::fill_fragment(acc[i][j], 0.f);

    const __half* gsrc[2];
    gsrc[0] = A + (size_t)m0 * K;
    gsrc[1] = W + (size_t)n0 * K;
    const int lr  = tid >> 2;
    const int lc8 = (tid & 3) * 8;

#define H_LOAD(dst4, kc) { \
    _Pragma("unroll") \
    for (int mtx = 0; mtx < 2; mtx++) \
        _Pragma("unroll") \
        for (int t = 0; t < 2; t++) \
            dst4[mtx][t] = *(const uint4*)(gsrc[mtx] + (size_t)(lr + t*64)*K + (kc) + lc8); }

#define H_STORE(bufbase, src4) { \
    _Pragma("unroll") \
    for (int mtx = 0; mtx < 2; mtx++) \
        _Pragma("unroll") \
        for (int t = 0; t < 2; t++) \
            *(uint4*)(bufbase + mtx*MATH_ + (lr + t*64)*LDH + lc8) = src4[mtx][t]; }

    {
        uint4 v[2][2];
        H_LOAD(v, 0);
        H_STORE(smh, v);
    }
    __syncthreads();

    const int NC = K >> 5;
    for (int c = 0; c < NC; c++) {
        const bool more = (c + 1 < NC);
        uint4 v[2][2];
        if (more) H_LOAD(v, (c + 1) * 32);

        {
            const __half* buf = smh + (size_t)(c & 1) * 2 * MATH_;
            const __half* sA = buf;
            const __half* sW = buf + MATH_;
#pragma unroll
            for (int kf = 0; kf < 2; kf++) {
                const int k0 = kf * 16;
                wmma::fragment<wmma::matrix_a, 16,16,16, __half, wmma::row_major> af[2];
#pragma unroll
                for (int i = 0; i < 2; i++)
                    wmma::load_matrix_sync(af[i], sA + (wm*32 + i*16)*LDH + k0, LDH);
#pragma unroll
                for (int j = 0; j < 4; j++) {
                    wmma::fragment<wmma::matrix_b, 16,16,16, __half, wmma::col_major> bf;
                    wmma::load_matrix_sync(bf, sW + (wn*64 + j*16)*LDH + k0, LDH);
#pragma unroll
                    for (int i = 0; i < 2; i++)
                        wmma::mma_sync(acc[i][j], af[i], bf, acc[i][j]);
                }
            }
        }
        if (more) {
            __half* buf = smh + (size_t)((c + 1) & 1) * 2 * MATH_;
            H_STORE(buf, v);
        }
        __syncthreads();
    }

    float* ep = (float*)smh + wid * (16*20);
    const int lane = tid & 31;
#pragma unroll
    for (int i = 0; i < 2; i++) {
#pragma unroll
        for (int j = 0; j < 4; j++) {
            wmma::store_matrix_sync(ep, acc[i][j], 20, wmma::mem_row_major);
            __syncwarp();
#pragma unroll
            for (int e = 0; e < 8; e++) {
                int idx = lane * 8 + e;
                int r = idx >> 4, cc = idx & 15;
                int m = m0 + wm*32 + i*16 + r;
                int n = n0 + wn*64 + j*16 + cc;
                float v = (ep[r*20 + cc] + bias[n]) * scale;
                if (OMODE == 0) {
                    C[(size_t)m * N + n] = v;
                } else {
                    Cf[(size_t)m * N + n] = __float2half_rn(v);
                }
            }
            __syncwarp();
        }
    }
}

// ---------------------------------------------------------------------------
// Flash attention v4: 64q x 128k tiles, fp16 single-term, 512 threads.
// Fragment-resident softmax:
//   - S accum initialized from mask via accumulator load (gmem, L2-hot)
//   - exp applied to accumulator fragment registers
//   - P written once as half via half-accumulator store
//   - row-sum l via ones-column appended to V (col 64), accumulated by the
//     same PV MMA pipeline in a dedicated fragment (wn2==0 warps)
// ---------------------------------------------------------------------------
#define LDQ 72
#define LDK 72
#define LDSF 136
#define OFF_Q  0                  // half 64x72  = 9216
#define OFF_K  9216               // half 128x72 = 18432 (fp32 sO alias at end)
#define OFF_V  27648              // half 128x72 = 18432
#define OFF_P  46080              // half 64x136 = 17408
#define FL_SMEM 63488

__global__ __launch_bounds__(512) void flash_f16(
    const __half* __restrict__ Qf, const __half* __restrict__ Kf,
    const __half* __restrict__ Vf, const float* __restrict__ mask,
    __half* __restrict__ AOf)
{
    extern __shared__ char smraw[];
    __half* sQ = (__half*)(smraw + OFF_Q);
    __half* sK = (__half*)(smraw + OFF_K);
    __half* sV = (__half*)(smraw + OFF_V);
    __half* sP = (__half*)(smraw + OFF_P);
    float*  sO  = (float*)(smraw + OFF_K);   // alias: 64x72 fp32 after loop
    float*  sLx = (float*)(smraw + OFF_Q);   // alias: 64x20 fp32 after loop

    const int tid = threadIdx.x;
    const int t0 = blockIdx.x * 64;
    const int h  = blockIdx.y;
    const int b  = blockIdx.z;
    const int wid = tid >> 5;
    const int wm = wid >> 3, wn = wid & 7;      // QK: 32 rows x 16 cols
    const int wm2 = wid >> 2, wn2 = wid & 3;    // PV: 16 rows x 16 cols

    // Q tile (64x64) + V padding cols (ones column at 64, zeros 65..71)
    {
        const __half* q = Qf + ((size_t)(b*TT + t0)) * EE + h*HD;
        int r = tid >> 3, c8 = (tid & 7) * 8;
        *(uint4*)&sQ[r*LDQ + c8] = *(const uint4*)(q + (size_t)r*EE + c8);
        if (tid < 128) {
            __half* vp = &sV[tid*LDK + 64];
            vp[0] = __float2half(1.f);
#pragma unroll
            for (int e = 1; e < 8; e++) vp[e] = __float2half(0.f);
        }
    }

    wmma::fragment<wmma::accumulator, 16, 16, 16, float> oacc, oextra;
    wmma::fill_fragment(oacc, 0.f);
    wmma::fill_fragment(oextra, 0.f);

    const __half* kb = Kf + (size_t)b * SS * EE + h*HD;
    const __half* vb = Vf + (size_t)b * SS * EE + h*HD;
    const float* mbase = mask + ((size_t)(b*TT + t0)) * TT;

    for (int st = 0; st < SS/128; st++) {
        const int sb = st * 128;
        const int s0b = sb & (TT - 1);

        __syncthreads();
        // K/V tiles: 128x64 halves each, 2 uint4 slots per thread each
#pragma unroll
        for (int t = 0; t < 2; t++) {
            int slot = tid + t*512;
            int r = slot >> 3, c8 = (slot & 7) * 8;
            size_t go = (size_t)(sb + r) * EE + c8;
            *(uint4*)&sK[r*LDK + c8] = *(const uint4*)(kb + go);
            *(uint4*)&sV[r*LDK + c8] = *(const uint4*)(vb + go);
        }
        __syncthreads();

        // S = mask + Q K^T, then exp in fragment registers -> P (half)
        {
            wmma::fragment<wmma::accumulator, 16, 16, 16, float> sacc[2];
#pragma unroll
            for (int i = 0; i < 2; i++)
                wmma::load_matrix_sync(sacc[i],
                    mbase + (size_t)(wm*32 + i*16)*TT + s0b + wn*16,
                    TT, wmma::mem_row_major);
#pragma unroll
            for (int k = 0; k < 4; k++) {
                wmma::fragment<wmma::matrix_a, 16,16,16, __half, wmma::row_major> af[2];
                wmma::fragment<wmma::matrix_b, 16,16,16, __half, wmma::col_major> bf;
#pragma unroll
                for (int i = 0; i < 2; i++)
                    wmma::load_matrix_sync(af[i], sQ + (wm*32 + i*16)*LDQ + k*16, LDQ);
                wmma::load_matrix_sync(bf, sK + (wn*16)*LDK + k*16, LDK);
#pragma unroll
                for (int i = 0; i < 2; i++)
                    wmma::mma_sync(sacc[i], af[i], bf, sacc[i]);
            }
#pragma unroll
            for (int i = 0; i < 2; i++) {
                wmma::fragment<wmma::accumulator, 16, 16, 16, __half> hacc;
#pragma unroll
                for (int e = 0; e < hacc.num_elements; e++)
                    hacc.x[e] = __float2half_rn(__expf(sacc[i].x[e]));
                wmma::store_matrix_sync(sP + (wm*32 + i*16)*LDSF + wn*16,
                                        hacc, LDSF, wmma::mem_row_major);
            }
        }
        __syncthreads();

        // O += P V; wn2==0 warps also accumulate the ones-column (row sums)
#pragma unroll
        for (int k = 0; k < 8; k++) {
            wmma::fragment<wmma::matrix_a, 16,16,16, __half, wmma::row_major> pf;
            wmma::load_matrix_sync(pf, sP + (wm2*16)*LDSF + k*16, LDSF);
            wmma::fragment<wmma::matrix_b, 16,16,16, __half, wmma::row_major> vf;
            wmma::load_matrix_sync(vf, sV + (k*16)*LDK + wn2*16, LDK);
            wmma::mma_sync(oacc, pf, vf, oacc);
            if (wn2 == 0) {
                wmma::fragment<wmma::matrix_b, 16,16,16, __half, wmma::row_major> vfx;
                wmma::load_matrix_sync(vfx, sV + (k*16)*LDK + 64, LDK);
                wmma::mma_sync(oextra, pf, vfx, oextra);
            }
        }
    }

    __syncthreads();   // sK/sQ reads done; safe to alias as sO/sLx
    wmma::store_matrix_sync(sO + (wm2*16)*LDQ + wn2*16, oacc, LDQ, wmma::mem_row_major);
    if (wn2 == 0)
        wmma::store_matrix_sync(sLx + (wm2*16)*20, oextra, 20, wmma::mem_row_major);
    __syncthreads();

    // write out fp16: AO[b, t0+r, h*HD + c] = sO / l  (l = sLx[r][0])
    {
        const int r = tid >> 3;
        const int c8 = (tid & 7) * 8;
        const float inv = 1.f / sLx[r*20];
        __half* ob = AOf + ((size_t)(b*TT + t0 + r)) * EE + h*HD + c8;
#pragma unroll
        for (int v = 0; v < 2; v++) {
            float4 o = *(const float4*)&sO[r*LDQ + c8 + v*4];
            __half2 p0 = __floats2half2_rn(o.x*inv, o.y*inv);
            __half2 p1 = __floats2half2_rn(o.z*inv, o.w*inv);
            *(__half2*)(ob + v*4)     = p0;
            *(__half2*)(ob + v*4 + 2) = p1;
        }
    }
}

// ---------------------------------------------------------------------------
extern "C" void kernel_launch(void* const* d_in, const int* in_sizes, int n_in,
                              void* d_out, int out_size) {
    const float* x    = (const float*)d_in[0];
    const float* mask = (const float*)d_in[1];
    const float* Wq   = (const float*)d_in[2];
    const float* bq   = (const float*)d_in[3];
    const float* Wk   = (const float*)d_in[4];
    const float* bk   = (const float*)d_in[5];
    const float* Wv   = (const float*)d_in[6];
    const float* bv   = (const float*)d_in[7];
    const float* Wo   = (const float*)d_in[8];
    const float* bo   = (const float*)d_in[9];
    float* out = (float*)d_out;

    __half *xf, *Wqf, *Wkf, *Wvf, *Wof, *Qfp, *Kfp, *Vfp, *AOfp;
    cudaGetSymbolAddress((void**)&xf, g_xf);
    cudaGetSymbolAddress((void**)&Wqf, g_Wqf);
    cudaGetSymbolAddress((void**)&Wkf, g_Wkf);
    cudaGetSymbolAddress((void**)&Wvf, g_Wvf);
    cudaGetSymbolAddress((void**)&Wof, g_Wof);
    cudaGetSymbolAddress((void**)&Qfp, g_Qf);
    cudaGetSymbolAddress((void**)&Kfp, g_Kf);
    cudaGetSymbolAddress((void**)&Vfp, g_Vf);
    cudaGetSymbolAddress((void**)&AOfp, g_AOf);

    static bool attr_done = false;
    if (!attr_done) {
        cudaFuncSetAttribute(sgemm_f16<0>, cudaFuncAttributeMaxDynamicSharedMemorySize, SH_SMEM);
        cudaFuncSetAttribute(sgemm_f16<2>, cudaFuncAttributeMaxDynamicSharedMemorySize, SH_SMEM);
        cudaFuncSetAttribute(flash_f16, cudaFuncAttributeMaxDynamicSharedMemorySize, FL_SMEM);
        attr_done = true;
    }

    // 1) convert inputs to fp16
    {
        int nx = BB*TT*EE/4;
        cvt_f16<<<(nx+255)/256, 256>>>(x, xf, nx);
        int nw1 = EE*EE/4;
        cvt_f16<<<(nw1+255)/256, 256>>>(Wq, Wqf, nw1);
        cvt_f16<<<(nw1+255)/256, 256>>>(Wo, Wof, nw1);
        int nw2 = MULT*EE*EE/4;
        cvt_f16<<<(nw2+255)/256, 256>>>(Wk, Wkf, nw2);
        cvt_f16<<<(nw2+255)/256, 256>>>(Wv, Wvf, nw2);
    }

    dim3 gblk(256);
    // 2) QKV projections (fp16 single-term GEMMs)
    sgemm_f16<2><<<dim3(EE/128, (BB*TT)/128), gblk, SH_SMEM>>>(
        xf, Wqf, bq, nullptr, Qfp, EE, EE, QSCALE);
    sgemm_f16<2><<<dim3((MULT*EE)/128, (BB*TT)/128), gblk, SH_SMEM>>>(
        xf, Wkf, bk, nullptr, Kfp, MULT*EE, EE, 1.f);
    sgemm_f16<2><<<dim3((MULT*EE)/128, (BB*TT)/128), gblk, SH_SMEM>>>(
        xf, Wvf, bv, nullptr, Vfp, MULT*EE, EE, 1.f);
    // 3) flash attention (fp16 single, fragment softmax) -> fp16 AO
    flash_f16<<<dim3(TT/64, HH, BB), dim3(512), FL_SMEM>>>(
        Qfp, Kfp, Vfp, mask, AOfp);
    // 4) output projection (fp16 single-term, fp32 out)
    sgemm_f16<0><<<dim3(EE/128, (BB*TT)/128), gblk, SH_SMEM>>>(
        AOfp, Wof, bo, out, nullptr, EE, EE, 1.f);
}

// round 15
// speedup vs baseline: 1.5115x; 1.1884x over previous
#include <cuda_runtime.h>
#include <cuda_bf16.h>
#include <cuda_fp16.h>
#include <mma.h>
#include <cstdint>

using namespace nvcuda;

// Problem constants
#define BB 4
#define TT 1024
#define EE 1024
#define HH 16
#define HD 64
#define MULT 2
#define SS (TT*MULT)
static constexpr float QSCALE = 0.125f;  // HD^-0.5

// Scratch (allocation-free rule: __device__ globals)
__device__ __half g_xf[BB*TT*EE];              // fp16 x
__device__ __half g_Wqf[EE*EE];
__device__ __half g_Wkf[MULT*EE*EE];
__device__ __half g_Wvf[MULT*EE*EE];
__device__ __half g_Wof[EE*EE];
__device__ __half g_Qf[BB*TT*EE];              // fp16 scaled q
__device__ __half g_Kf[BB*SS*EE];
__device__ __half g_Vf[BB*SS*EE];
__device__ __half g_AOf[BB*TT*EE];             // fp16 attention output
// bias tiles: [16][N] fp32, all rows equal to bias (for accumulator init)
__device__ float g_bTq[16*EE];
__device__ float g_bTk[16*MULT*EE];
__device__ float g_bTv[16*MULT*EE];
__device__ float g_bTo[16*EE];

// ---------------------------------------------------------------------------
// Fused fp32 -> fp16 convert for all five inputs (segment select).
// ---------------------------------------------------------------------------
#define N4_X  (BB*TT*EE/4)
#define N4_W1 (EE*EE/4)
#define N4_W2 (MULT*EE*EE/4)
#define N4_TOT (N4_X + 2*N4_W1 + 2*N4_W2)

__global__ __launch_bounds__(256) void cvt_all(
    const float* __restrict__ x,  const float* __restrict__ Wq,
    const float* __restrict__ Wk, const float* __restrict__ Wv,
    const float* __restrict__ Wo)
{
    int i = blockIdx.x * blockDim.x + threadIdx.x;
    if (i >= N4_TOT) return;
    const float* src; __half* dst; int off;
    if (i < N4_X) { src = x; dst = g_xf; off = i; }
    else if (i < N4_X + N4_W1) { src = Wq; dst = g_Wqf; off = i - N4_X; }
    else if (i < N4_X + N4_W1 + N4_W2) { src = Wk; dst = g_Wkf; off = i - N4_X - N4_W1; }
    else if (i < N4_X + N4_W1 + 2*N4_W2) { src = Wv; dst = g_Wvf; off = i - N4_X - N4_W1 - N4_W2; }
    else { src = Wo; dst = g_Wof; off = i - N4_X - N4_W1 - 2*N4_W2; }
    float4 v = ((const float4*)src)[off];
    ((__half2*)dst)[off*2]   = __floats2half2_rn(v.x, v.y);
    ((__half2*)dst)[off*2+1] = __floats2half2_rn(v.z, v.w);
}

// Bias tile builder: col c of matrix seg gets bias[c] in all 16 rows.
__global__ __launch_bounds__(256) void bias_tiles(
    const float* __restrict__ bq, const float* __restrict__ bk,
    const float* __restrict__ bv, const float* __restrict__ bo)
{
    int i = blockIdx.x * blockDim.x + threadIdx.x;   // 0 .. 6143
    float v; float* t; int n, N;
    if (i < EE)               { v = bq[i];           t = g_bTq; n = i;           N = EE; }
    else if (i < EE+2048)     { v = bk[i-EE];        t = g_bTk; n = i-EE;        N = MULT*EE; }
    else if (i < EE+4096)     { v = bv[i-EE-2048];   t = g_bTv; n = i-EE-2048;   N = MULT*EE; }
    else if (i < EE+4096+EE)  { v = bo[i-EE-4096];   t = g_bTo; n = i-EE-4096;   N = EE; }
    else return;
#pragma unroll
    for (int r = 0; r < 16; r++) t[r*N + n] = v;
}

// ---------------------------------------------------------------------------
// fp16 single-term GEMM (fp32 accum):  C = (A W^T + bias) * scale.
// Bias via accumulator init from bias tile; direct fragment store to gmem.
// OMODE 0: fp32 out (C). 2: fp16 out (Cf).
// 256 threads = 8 warps in 4x2 grid; warp tile 32x64; 2 CTAs/SM.
// ---------------------------------------------------------------------------
#define LDH 40
#define MATH_ (128*LDH)
#define SH_SMEM (2*2*MATH_*2)

template<int OMODE>
__global__ __launch_bounds__(256, 2) void sgemm_f16(
    const __half* __restrict__ A, const __half* __restrict__ W,
    const float* __restrict__ biasT, float* __restrict__ C,
    __half* __restrict__ Cf,
    int N, int K, float scale)
{
    extern __shared__ __half smh[];

    const int tid = threadIdx.x;
    const int m0 = blockIdx.y * 128;
    const int n0 = blockIdx.x * 128;
    const int wid = tid >> 5;
    const int wm = wid >> 1;
    const int wn = wid & 1;

    wmma::fragment<wmma::accumulator, 16, 16, 16, float> acc[2][4];
#pragma unroll
    for (int i = 0; i < 2; i++)
#pragma unroll
        for (int j = 0; j < 4; j++)
            wmma::load_matrix_sync(acc[i][j], biasT + n0 + wn*64 + j*16,
                                   N, wmma::mem_row_major);

    const __half* gsrc[2];
    gsrc[0] = A + (size_t)m0 * K;
    gsrc[1] = W + (size_t)n0 * K;
    const int lr  = tid >> 2;
    const int lc8 = (tid & 3) * 8;

#define H_LOAD(dst4, kc) { \
    _Pragma("unroll") \
    for (int mtx = 0; mtx < 2; mtx++) \
        _Pragma("unroll") \
        for (int t = 0; t < 2; t++) \
            dst4[mtx][t] = *(const uint4*)(gsrc[mtx] + (size_t)(lr + t*64)*K + (kc) + lc8); }

#define H_STORE(bufbase, src4) { \
    _Pragma("unroll") \
    for (int mtx = 0; mtx < 2; mtx++) \
        _Pragma("unroll") \
        for (int t = 0; t < 2; t++) \
            *(uint4*)(bufbase + mtx*MATH_ + (lr + t*64)*LDH + lc8) = src4[mtx][t]; }

    {
        uint4 v[2][2];
        H_LOAD(v, 0);
        H_STORE(smh, v);
    }
    __syncthreads();

    const int NC = K >> 5;
    for (int c = 0; c < NC; c++) {
        const bool more = (c + 1 < NC);
        uint4 v[2][2];
        if (more) H_LOAD(v, (c + 1) * 32);

        {
            const __half* buf = smh + (size_t)(c & 1) * 2 * MATH_;
            const __half* sA = buf;
            const __half* sW = buf + MATH_;
#pragma unroll
            for (int kf = 0; kf < 2; kf++) {
                const int k0 = kf * 16;
                wmma::fragment<wmma::matrix_a, 16,16,16, __half, wmma::row_major> af[2];
#pragma unroll
                for (int i = 0; i < 2; i++)
                    wmma::load_matrix_sync(af[i], sA + (wm*32 + i*16)*LDH + k0, LDH);
#pragma unroll
                for (int j = 0; j < 4; j++) {
                    wmma::fragment<wmma::matrix_b, 16,16,16, __half, wmma::col_major> bf;
                    wmma::load_matrix_sync(bf, sW + (wn*64 + j*16)*LDH + k0, LDH);
#pragma unroll
                    for (int i = 0; i < 2; i++)
                        wmma::mma_sync(acc[i][j], af[i], bf, acc[i][j]);
                }
            }
        }
        if (more) {
            __half* buf = smh + (size_t)((c + 1) & 1) * 2 * MATH_;
            H_STORE(buf, v);
        }
        __syncthreads();
    }

    // epilogue: scale in fragment, store directly to gmem
#pragma unroll
    for (int i = 0; i < 2; i++) {
#pragma unroll
        for (int j = 0; j < 4; j++) {
            const int m = m0 + wm*32 + i*16;
            const int n = n0 + wn*64 + j*16;
            if (OMODE == 0) {
                if (scale != 1.f) {
#pragma unroll
                    for (int e = 0; e < acc[i][j].num_elements; e++)
                        acc[i][j].x[e] *= scale;
                }
                wmma::store_matrix_sync(C + (size_t)m * N + n, acc[i][j],
                                        N, wmma::mem_row_major);
            } else {
                wmma::fragment<wmma::accumulator, 16, 16, 16, __half> hacc;
#pragma unroll
                for (int e = 0; e < hacc.num_elements; e++)
                    hacc.x[e] = __float2half_rn(acc[i][j].x[e] * scale);
                wmma::store_matrix_sync(Cf + (size_t)m * N + n, hacc,
                                        N, wmma::mem_row_major);
            }
        }
    }
}

// ---------------------------------------------------------------------------
// Flash attention v5: 64q x 128k tiles, fp16 single-term, 512 threads.
// Fragment softmax (R14); PV row-sum work spread: warp (wm2,wn2) does the
// ones-column MMA only for k in {2*wn2, 2*wn2+1}; partials summed via smem.
// ---------------------------------------------------------------------------
#define LDQ 72
#define LDK 72
#define LDSF 136
#define OFF_Q  0                  // half 64x72  = 9216
#define OFF_K  9216               // half 128x72 = 18432 (fp32 sO alias at end)
#define OFF_V  27648              // half 128x72 = 18432
#define OFF_P  46080              // half 64x136 = 17408 (fp32 sLpart alias)
#define FL_SMEM 63488

__global__ __launch_bounds__(512) void flash_f16(
    const __half* __restrict__ Qf, const __half* __restrict__ Kf,
    const __half* __restrict__ Vf, const float* __restrict__ mask,
    __half* __restrict__ AOf)
{
    extern __shared__ char smraw[];
    __half* sQ = (__half*)(smraw + OFF_Q);
    __half* sK = (__half*)(smraw + OFF_K);
    __half* sV = (__half*)(smraw + OFF_V);
    __half* sP = (__half*)(smraw + OFF_P);
    float*  sO     = (float*)(smraw + OFF_K);   // alias after loop: 64x72 fp32
    float*  sLpart = (float*)(smraw + OFF_P);   // alias after loop: 4x64x16 fp32

    const int tid = threadIdx.x;
    const int t0 = blockIdx.x * 64;
    const int h  = blockIdx.y;
    const int b  = blockIdx.z;
    const int wid = tid >> 5;
    const int wm = wid >> 3, wn = wid & 7;      // QK: 32 rows x 16 cols
    const int wm2 = wid >> 2, wn2 = wid & 3;    // PV: 16 rows x 16 cols

    // Q tile (64x64) + V padding cols (ones column at 64, zeros 65..71)
    {
        const __half* q = Qf + ((size_t)(b*TT + t0)) * EE + h*HD;
        int r = tid >> 3, c8 = (tid & 7) * 8;
        *(uint4*)&sQ[r*LDQ + c8] = *(const uint4*)(q + (size_t)r*EE + c8);
        if (tid < 128) {
            __half* vp = &sV[tid*LDK + 64];
            vp[0] = __float2half(1.f);
#pragma unroll
            for (int e = 1; e < 8; e++) vp[e] = __float2half(0.f);
        }
    }

    wmma::fragment<wmma::accumulator, 16, 16, 16, float> oacc, oextra;
    wmma::fill_fragment(oacc, 0.f);
    wmma::fill_fragment(oextra, 0.f);

    const __half* kb = Kf + (size_t)b * SS * EE + h*HD;
    const __half* vb = Vf + (size_t)b * SS * EE + h*HD;
    const float* mbase = mask + ((size_t)(b*TT + t0)) * TT;

    for (int st = 0; st < SS/128; st++) {
        const int sb = st * 128;
        const int s0b = sb & (TT - 1);

        __syncthreads();
#pragma unroll
        for (int t = 0; t < 2; t++) {
            int slot = tid + t*512;
            int r = slot >> 3, c8 = (slot & 7) * 8;
            size_t go = (size_t)(sb + r) * EE + c8;
            *(uint4*)&sK[r*LDK + c8] = *(const uint4*)(kb + go);
            *(uint4*)&sV[r*LDK + c8] = *(const uint4*)(vb + go);
        }
        __syncthreads();

        // S = mask + Q K^T, exp in fragment registers -> P (half)
        {
            wmma::fragment<wmma::accumulator, 16, 16, 16, float> sacc[2];
#pragma unroll
            for (int i = 0; i < 2; i++)
                wmma::load_matrix_sync(sacc[i],
                    mbase + (size_t)(wm*32 + i*16)*TT + s0b + wn*16,
                    TT, wmma::mem_row_major);
#pragma unroll
            for (int k = 0; k < 4; k++) {
                wmma::fragment<wmma::matrix_a, 16,16,16, __half, wmma::row_major> af[2];
                wmma::fragment<wmma::matrix_b, 16,16,16, __half, wmma::col_major> bf;
#pragma unroll
                for (int i = 0; i < 2; i++)
                    wmma::load_matrix_sync(af[i], sQ + (wm*32 + i*16)*LDQ + k*16, LDQ);
                wmma::load_matrix_sync(bf, sK + (wn*16)*LDK + k*16, LDK);
#pragma unroll
                for (int i = 0; i < 2; i++)
                    wmma::mma_sync(sacc[i], af[i], bf, sacc[i]);
            }
#pragma unroll
            for (int i = 0; i < 2; i++) {
                wmma::fragment<wmma::accumulator, 16, 16, 16, __half> hacc;
#pragma unroll
                for (int e = 0; e < hacc.num_elements; e++)
                    hacc.x[e] = __float2half_rn(__expf(sacc[i].x[e]));
                wmma::store_matrix_sync(sP + (wm*32 + i*16)*LDSF + wn*16,
                                        hacc, LDSF, wmma::mem_row_major);
            }
        }
        __syncthreads();

        // O += P V; l-MMA spread: this warp covers k = 2*wn2, 2*wn2+1
#pragma unroll
        for (int k = 0; k < 8; k++) {
            wmma::fragment<wmma::matrix_a, 16,16,16, __half, wmma::row_major> pf;
            wmma::load_matrix_sync(pf, sP + (wm2*16)*LDSF + k*16, LDSF);
            wmma::fragment<wmma::matrix_b, 16,16,16, __half, wmma::row_major> vf;
            wmma::load_matrix_sync(vf, sV + (k*16)*LDK + wn2*16, LDK);
            wmma::mma_sync(oacc, pf, vf, oacc);
            if ((k >> 1) == wn2) {
                wmma::fragment<wmma::matrix_b, 16,16,16, __half, wmma::row_major> vfx;
                wmma::load_matrix_sync(vfx, sV + (k*16)*LDK + 64, LDK);
                wmma::mma_sync(oextra, pf, vfx, oextra);
            }
        }
    }

    __syncthreads();   // all smem tile reads done; safe to alias
    wmma::store_matrix_sync(sO + (wm2*16)*LDQ + wn2*16, oacc, LDQ, wmma::mem_row_major);
    wmma::store_matrix_sync(sLpart + (size_t)(wn2*64 + wm2*16)*16, oextra,
                            16, wmma::mem_row_major);
    __syncthreads();

    // write out fp16: AO[b, t0+r, h*HD + c] = sO / l
    {
        const int r = tid >> 3;
        const int c8 = (tid & 7) * 8;
        const float l = sLpart[(0*64 + r)*16] + sLpart[(1*64 + r)*16]
                      + sLpart[(2*64 + r)*16] + sLpart[(3*64 + r)*16];
        const float inv = 1.f / l;
        __half* ob = AOf + ((size_t)(b*TT + t0 + r)) * EE + h*HD + c8;
#pragma unroll
        for (int v = 0; v < 2; v++) {
            float4 o = *(const float4*)&sO[r*LDQ + c8 + v*4];
            __half2 p0 = __floats2half2_rn(o.x*inv, o.y*inv);
            __half2 p1 = __floats2half2_rn(o.z*inv, o.w*inv);
            *(__half2*)(ob + v*4)     = p0;
            *(__half2*)(ob + v*4 + 2) = p1;
        }
    }
}

// ---------------------------------------------------------------------------
extern "C" void kernel_launch(void* const* d_in, const int* in_sizes, int n_in,
                              void* d_out, int out_size) {
    const float* x    = (const float*)d_in[0];
    const float* mask = (const float*)d_in[1];
    const float* Wq   = (const float*)d_in[2];
    const float* bq   = (const float*)d_in[3];
    const float* Wk   = (const float*)d_in[4];
    const float* bk   = (const float*)d_in[5];
    const float* Wv   = (const float*)d_in[6];
    const float* bv   = (const float*)d_in[7];
    const float* Wo   = (const float*)d_in[8];
    const float* bo   = (const float*)d_in[9];
    float* out = (float*)d_out;

    __half *xf, *Wqf, *Wkf, *Wvf, *Wof, *Qfp, *Kfp, *Vfp, *AOfp;
    float *bTq, *bTk, *bTv, *bTo;
    cudaGetSymbolAddress((void**)&xf, g_xf);
    cudaGetSymbolAddress((void**)&Wqf, g_Wqf);
    cudaGetSymbolAddress((void**)&Wkf, g_Wkf);
    cudaGetSymbolAddress((void**)&Wvf, g_Wvf);
    cudaGetSymbolAddress((void**)&Wof, g_Wof);
    cudaGetSymbolAddress((void**)&Qfp, g_Qf);
    cudaGetSymbolAddress((void**)&Kfp, g_Kf);
    cudaGetSymbolAddress((void**)&Vfp, g_Vf);
    cudaGetSymbolAddress((void**)&AOfp, g_AOf);
    cudaGetSymbolAddress((void**)&bTq, g_bTq);
    cudaGetSymbolAddress((void**)&bTk, g_bTk);
    cudaGetSymbolAddress((void**)&bTv, g_bTv);
    cudaGetSymbolAddress((void**)&bTo, g_bTo);

    static bool attr_done = false;
    if (!attr_done) {
        cudaFuncSetAttribute(sgemm_f16<0>, cudaFuncAttributeMaxDynamicSharedMemorySize, SH_SMEM);
        cudaFuncSetAttribute(sgemm_f16<2>, cudaFuncAttributeMaxDynamicSharedMemorySize, SH_SMEM);
        cudaFuncSetAttribute(flash_f16, cudaFuncAttributeMaxDynamicSharedMemorySize, FL_SMEM);
        attr_done = true;
    }

    // 1) convert inputs to fp16 + build bias tiles
    cvt_all<<<(N4_TOT + 255)/256, 256>>>(x, Wq, Wk, Wv, Wo);
    bias_tiles<<<(EE*2 + 4096 + 255)/256, 256>>>(bq, bk, bv, bo);

    dim3 gblk(256);
    // 2) QKV projections (fp16 single-term GEMMs)
    sgemm_f16<2><<<dim3(EE/128, (BB*TT)/128), gblk, SH_SMEM>>>(
        xf, Wqf, bTq, nullptr, Qfp, EE, EE, QSCALE);
    sgemm_f16<2><<<dim3((MULT*EE)/128, (BB*TT)/128), gblk, SH_SMEM>>>(
        xf, Wkf, bTk, nullptr, Kfp, MULT*EE, EE, 1.f);
    sgemm_f16<2><<<dim3((MULT*EE)/128, (BB*TT)/128), gblk, SH_SMEM>>>(
        xf, Wvf, bTv, nullptr, Vfp, MULT*EE, EE, 1.f);
    // 3) flash attention (fp16 single, fragment softmax) -> fp16 AO
    flash_f16<<<dim3(TT/64, HH, BB), dim3(512), FL_SMEM>>>(
        Qfp, Kfp, Vfp, mask, AOfp);
    // 4) output projection (fp16 single-term, fp32 out)
    sgemm_f16<0><<<dim3(EE/128, (BB*TT)/128), gblk, SH_SMEM>>>(
        AOfp, Wof, bTo, out, nullptr, EE, EE, 1.f);
}